// round 9
// baseline (speedup 1.0000x reference)
#include <cuda_runtime.h>
#include <cuda_bf16.h>
#include <cstdint>

#define NUM_TAGS 32
#define START_TAG 30
#define STOP_TAG 31
#define MAX_B 1024
#define SEQ_S 512
#define LN2F 0.6931471805599453f
#define FULLMASK 0xffffffffu

__device__ float g_partial[MAX_B];
__device__ unsigned g_done = 0;

__device__ __forceinline__ unsigned long long fma2(unsigned long long a,
                                                   unsigned long long b,
                                                   unsigned long long c) {
    unsigned long long d;
    asm("fma.rn.f32x2 %0, %1, %2, %3;" : "=l"(d) : "l"(a), "l"(b), "l"(c));
    return d;
}
__device__ __forceinline__ unsigned long long mul2(unsigned long long a,
                                                   unsigned long long b) {
    unsigned long long d;
    asm("mul.rn.f32x2 %0, %1, %2;" : "=l"(d) : "l"(a), "l"(b));
    return d;
}
__device__ __forceinline__ unsigned long long add2(unsigned long long a,
                                                   unsigned long long b) {
    unsigned long long d;
    asm("add.rn.f32x2 %0, %1, %2;" : "=l"(d) : "l"(a), "l"(b));
    return d;
}
__device__ __forceinline__ void unpack2(unsigned long long v, float& lo, float& hi) {
    asm("mov.b64 {%0, %1}, %2;" : "=f"(lo), "=f"(hi) : "l"(v));
}
__device__ __forceinline__ unsigned long long pack2(float lo, float hi) {
    unsigned long long v;
    asm("mov.b64 %0, {%1, %2};" : "=l"(v) : "f"(lo), "f"(hi));
    return v;
}

// 2 chains per warp (half-warp each), 2 tags per lane packed in f32x2.
// Matvec broadcast via width-16 SHFL (no smem round trip on the chain).
__global__ __launch_bounds__(128, 1) void crf_forward_kernel(
    const float* __restrict__ feats,       // [B, 512, 32]
    const int*   __restrict__ labels,      // [B, 512]
    const int*   __restrict__ lengths,     // [B]
    const float* __restrict__ transitions, // [32, 32]
    float* __restrict__ out, int B, int nblocks)
{
    __shared__ float sT[NUM_TAGS * NUM_TAGS];
    __shared__ float sred[128];
    __shared__ int sIsLast;

    const int tid  = threadIdx.x;
    const int w    = tid >> 5;
    const int lane = tid & 31;
    const int half = lane >> 4;       // which chain in this warp
    const int r    = lane & 15;       // lane within chain; owns tags 2r, 2r+1

    #pragma unroll
    for (int k = 0; k < 8; k++)
        sT[tid + k * 128] = transitions[tid + k * 128];
    __syncthreads();

    const int gw = blockIdx.x * 4 + w;        // warp id
    const int b  = 2 * gw + half;             // this half-warp's batch
    const bool vb = (b < B);
    const bool active = (2 * gw) < B;         // warp-uniform

    if (active) {
        // Packed transition columns for this lane's two output tags:
        // EA[p] = { E[2p][2r],   E[2p+1][2r]   },  jA = 2r
        // EB[p] = { E[2p][2r+1], E[2p+1][2r+1] },  jB = 2r+1
        unsigned long long EA[16], EB[16];
        #pragma unroll
        for (int p = 0; p < 16; p++) {
            EA[p] = pack2(__expf(sT[(2 * p) * NUM_TAGS + 2 * r]),
                          __expf(sT[(2 * p + 1) * NUM_TAGS + 2 * r]));
            EB[p] = pack2(__expf(sT[(2 * p) * NUM_TAGS + 2 * r + 1]),
                          __expf(sT[(2 * p + 1) * NUM_TAGS + 2 * r + 1]));
        }

        const int len = vb ? lengths[b] : 0;
        const float2* fb2 = (const float2*)(feats +
                             (size_t)(vb ? b : 0) * SEQ_S * NUM_TAGS);
        const unsigned hmask = half ? 0xFFFF0000u : 0x0000FFFFu;
        const int maxlen = (int)__reduce_max_sync(FULLMASK, (unsigned)len);

        // t = 0 init
        float2 f0 = fb2[r];
        unsigned long long pa = pack2(
            __expf(f0.x + sT[START_TAG * NUM_TAGS + 2 * r]),
            __expf(f0.y + sT[START_TAG * NUM_TAGS + 2 * r + 1]));
        int ilog = 0;
        unsigned prev_mb = 127u << 23;

        // Prefetch rows 1..7 and 8..15
        float2 fpre[7], fX[8], fY[8];
        #pragma unroll
        for (int d = 0; d < 7; d++) fpre[d] = fb2[(1 + d) * 16 + r];
        #pragma unroll
        for (int d = 0; d < 8; d++) fX[d] = fb2[(8 + d) * 16 + r];

// One recursion step for both chains. 32 width-16 SHFLs broadcast the packed
// alpha pairs within each half-warp; 32 fma2 accumulate both output tags.
#define CRF_STEP(F2, VALID)                                                    \
    {                                                                          \
        float palo_, pahi_; unpack2(pa, palo_, pahi_);                         \
        unsigned long long pp[16];                                             \
        _Pragma("unroll")                                                      \
        for (int p = 0; p < 16; p++) {                                         \
            float lo_ = __shfl_sync(FULLMASK, palo_, p, 16);                   \
            float hi_ = __shfl_sync(FULLMASK, pahi_, p, 16);                   \
            pp[p] = pack2(lo_, hi_);                                           \
        }                                                                      \
        unsigned long long A0 = mul2(pp[0], EA[0]);                            \
        unsigned long long A1 = mul2(pp[1], EA[1]);                            \
        unsigned long long A2 = mul2(pp[2], EA[2]);                            \
        unsigned long long A3 = mul2(pp[3], EA[3]);                            \
        unsigned long long B0 = mul2(pp[0], EB[0]);                            \
        unsigned long long B1 = mul2(pp[1], EB[1]);                            \
        unsigned long long B2 = mul2(pp[2], EB[2]);                            \
        unsigned long long B3 = mul2(pp[3], EB[3]);                            \
        A0 = fma2(pp[4],  EA[4],  A0);  B0 = fma2(pp[4],  EB[4],  B0);         \
        A1 = fma2(pp[5],  EA[5],  A1);  B1 = fma2(pp[5],  EB[5],  B1);         \
        A2 = fma2(pp[6],  EA[6],  A2);  B2 = fma2(pp[6],  EB[6],  B2);         \
        A3 = fma2(pp[7],  EA[7],  A3);  B3 = fma2(pp[7],  EB[7],  B3);         \
        A0 = fma2(pp[8],  EA[8],  A0);  B0 = fma2(pp[8],  EB[8],  B0);         \
        A1 = fma2(pp[9],  EA[9],  A1);  B1 = fma2(pp[9],  EB[9],  B1);         \
        A2 = fma2(pp[10], EA[10], A2);  B2 = fma2(pp[10], EB[10], B2);         \
        A3 = fma2(pp[11], EA[11], A3);  B3 = fma2(pp[11], EB[11], B3);         \
        A0 = fma2(pp[12], EA[12], A0);  B0 = fma2(pp[12], EB[12], B0);         \
        A1 = fma2(pp[13], EA[13], A1);  B1 = fma2(pp[13], EB[13], B1);         \
        A2 = fma2(pp[14], EA[14], A2);  B2 = fma2(pp[14], EB[14], B2);         \
        A3 = fma2(pp[15], EA[15], A3);  B3 = fma2(pp[15], EB[15], B3);         \
        A0 = add2(A0, A1); A2 = add2(A2, A3); A0 = add2(A0, A2);               \
        B0 = add2(B0, B1); B2 = add2(B2, B3); B0 = add2(B0, B2);               \
        float sAlo, sAhi; unpack2(A0, sAlo, sAhi);                             \
        float sBlo, sBhi; unpack2(B0, sBlo, sBhi);                             \
        const float na_ = (sAlo + sAhi) * __expf((F2).x);                      \
        const float nb_ = (sBlo + sBhi) * __expf((F2).y);                      \
        const unsigned long long npa_ = pack2(na_, nb_);                       \
        pa = (VALID) ? npa_ : pa;                                              \
    }

#define CRF_RENORM                                                             \
    {                                                                          \
        int e_ = (int)((prev_mb >> 23) & 0xff);                                \
        int sc_ = 254 - e_; sc_ = (sc_ < 1) ? 1 : sc_;                         \
        sc_ = (sc_ > 254) ? 254 : sc_;                                         \
        const float s_ = __int_as_float(sc_ << 23);                            \
        pa = mul2(pa, pack2(s_, s_));                                          \
        ilog += 127 - sc_;                                                     \
        float lo_, hi_; unpack2(pa, lo_, hi_);                                 \
        prev_mb = __reduce_max_sync(hmask,                                     \
                      __float_as_uint(fmaxf(lo_, hi_)));                       \
    }

// 8-step superblock: prefetch next 8 rows, 8 masked steps, renorm.
#define CRF_SUPER(CUR, NXT, TBASE)                                             \
    {                                                                          \
        _Pragma("unroll")                                                      \
        for (int u = 0; u < 8; u++) {                                          \
            int r_ = (TBASE) + 8 + u; r_ = (r_ < SEQ_S) ? r_ : (SEQ_S - 1);    \
            NXT[u] = fb2[r_ * 16 + r];                                         \
        }                                                                      \
        _Pragma("unroll")                                                      \
        for (int u = 0; u < 8; u++) {                                          \
            CRF_STEP(CUR[u], ((TBASE) + u) < len);                             \
        }                                                                      \
        CRF_RENORM;                                                            \
    }

        // Prologue: steps t = 1..7
        #pragma unroll
        for (int u = 0; u < 7; u++) {
            CRF_STEP(fpre[u], (1 + u) < len);
        }
        CRF_RENORM;

        // Main loop: masked ping-pong superblocks to warp-max length
        int t = 8;
        while (t < maxlen) {
            CRF_SUPER(fX, fY, t);
            t += 8;
            if (t >= maxlen) break;
            CRF_SUPER(fY, fX, t);
            t += 8;
        }
#undef CRF_STEP
#undef CRF_RENORM
#undef CRF_SUPER

        // Forward score: sum packed pair, reduce across half-warp
        float plo, phi; unpack2(pa, plo, phi);
        float tot = plo + phi;
        #pragma unroll
        for (int off = 8; off >= 1; off >>= 1)
            tot += __shfl_xor_sync(FULLMASK, tot, off, 16);
        const float fwd = __logf(tot) + (float)ilog * LN2F;

        // Gold-score epilogues: one chain at a time, full warp gathers.
        #pragma unroll 1
        for (int c = 0; c < 2; c++) {
            const int b_c = 2 * gw + c;
            if (b_c >= B) continue;                      // warp-uniform
            const int len_c  = __shfl_sync(FULLMASK, len, c * 16);
            const float fwd_c = __shfl_sync(FULLMASK, fwd, c * 16);
            const float* fbc = feats + (size_t)b_c * SEQ_S * NUM_TAGS;
            const int labBase = b_c * SEQ_S;

            float epacc = 0.0f;
            for (int base = 0; base < len_c; base += 32) {
                const int pos = base + lane;
                const bool v = pos < len_c;
                const int cp = v ? pos : (len_c - 1);
                const int lab = labels[labBase + cp];
                const float fv = fbc[cp * NUM_TAGS + lab];
                float contrib = fv;
                if (pos >= 1) {
                    const int lp = labels[labBase + cp - 1];
                    contrib += sT[lp * NUM_TAGS + lab];
                }
                if (v) epacc += contrib;
            }
            #pragma unroll
            for (int off = 16; off >= 1; off >>= 1)
                epacc += __shfl_xor_sync(FULLMASK, epacc, off);

            const int lab0 = labels[labBase];
            const int labL = labels[labBase + len_c - 1];
            const float gold = epacc + sT[START_TAG * NUM_TAGS + lab0]
                                     + sT[labL * NUM_TAGS + STOP_TAG];

            if (lane == 0) g_partial[b_c] = fwd_c - gold;
        }
    }

    // Fused final reduction: last block to finish sums all partials.
    __syncthreads();
    if (tid == 0) {
        __threadfence();
        unsigned rdone = atomicAdd(&g_done, 1u);
        sIsLast = (rdone == (unsigned)(nblocks - 1));
    }
    __syncthreads();
    if (sIsLast) {
        __threadfence();
        float s = 0.0f;
        for (int i = tid; i < B; i += 128) s += g_partial[i];
        sred[tid] = s;
        __syncthreads();
        if (tid < 64) sred[tid] += sred[tid + 64];
        __syncthreads();
        if (tid < 32) {
            float v2 = sred[tid] + sred[tid + 32];
            #pragma unroll
            for (int off = 16; off >= 1; off >>= 1)
                v2 += __shfl_xor_sync(FULLMASK, v2, off);
            if (tid == 0) {
                out[0] = v2 / (float)B;
                g_done = 0;   // reset for next graph replay
            }
        }
    }
}

extern "C" void kernel_launch(void* const* d_in, const int* in_sizes, int n_in,
                              void* d_out, int out_size)
{
    const float* feats       = (const float*)d_in[0];
    const int*   labels      = (const int*)d_in[1];
    const int*   lengths     = (const int*)d_in[2];
    const float* transitions = (const float*)d_in[3];
    float* out = (float*)d_out;

    const int B = in_sizes[2];
    const int nwarps = (B + 1) / 2;        // 2 chains per warp
    const int blocks = (nwarps + 3) / 4;   // 4 warps per block

    crf_forward_kernel<<<blocks, 128>>>(feats, labels, lengths, transitions,
                                        out, B, blocks);
}